// round 5
// baseline (speedup 1.0000x reference)
#include <cuda_runtime.h>
#include <stdint.h>

// Problem constants (fixed by setup_inputs)
#define Bn 8
#define Hn 1024
#define Wn 1024
#define Cn 3
#define Mn (Hn*Wn*Cn)          // 3145728 per batch
#define HWn (Hn*Wn)            // 1048576
#define Rn 1572864u            // ceil(M/2)
#define NBINS 8192
#define CAND_CAP 262144
#define WIN_LO_BIN 2176u       // bins [2176, 6016) == values in (-2^-7, +2^-7)
#define WIN_HI_BIN 6016u

// ---- device scratch (static globals; no allocation) ----
__device__ unsigned int g_hist[Bn][NBINS];
__device__ unsigned int g_cand[Bn][CAND_CAP];
__device__ unsigned int g_cnt[Bn];
__device__ unsigned int g_rank[Bn];
__device__ int          g_fallback[Bn];
__device__ unsigned int g_fbin[Bn];
__device__ float        g_thr[Bn];
__device__ float        g_zsum;

__device__ __forceinline__ unsigned int f2key(float f) {
    unsigned int u = __float_as_uint(f);
    return (u & 0x80000000u) ? ~u : (u | 0x80000000u);   // monotone: larger key == larger float
}
__device__ __forceinline__ float key2f(unsigned int k) {
    return (k & 0x80000000u) ? __uint_as_float(k & 0x7fffffffu)
                             : __uint_as_float(~k);
}

// Warp-aggregated push of flagged keys into g_cand[b]. ALL 32 lanes must call.
__device__ __forceinline__ void warp_push(int b, bool m, unsigned int key) {
    const unsigned int lane = threadIdx.x & 31u;
    unsigned int mask = __ballot_sync(0xffffffffu, m);
    unsigned int cnt = __popc(mask);
    unsigned int base = 0u;
    if (lane == 0u && cnt) base = atomicAdd(&g_cnt[b], cnt);
    base = __shfl_sync(0xffffffffu, base, 0);   // uniform: every lane executes
    if (m) {
        unsigned int pos = base + __popc(mask & ((1u << lane) - 1u));
        if (pos < CAND_CAP) g_cand[b][pos] = key;
    }
}

// ---- K0: zero scratch (graph replays reuse globals) ----
__global__ void k_init() {
    int tid = blockIdx.x * blockDim.x + threadIdx.x;
    int stride = gridDim.x * blockDim.x;
    unsigned int* h = (unsigned int*)g_hist;
    for (int i = tid; i < Bn * NBINS; i += stride) h[i] = 0u;
    if (tid < Bn) g_cnt[tid] = 0u;
    if (tid == 0) g_zsum = 0.f;
}

// ---- K1: per-batch 13-bit histogram + window candidate collect ----
// grid (24, Bn), 1024 threads. 24*1024 divides Mn/4 exactly -> uniform warp trips.
__global__ void k_hist(const float* __restrict__ Y) {
    __shared__ unsigned int sh[NBINS];
    const int b = blockIdx.y;
    for (int i = threadIdx.x; i < NBINS; i += blockDim.x) sh[i] = 0u;
    __syncthreads();

    const float4* Yb = (const float4*)(Y + (size_t)b * Mn);
    const int n4 = Mn / 4;                       // 786432
    const int stride = gridDim.x * blockDim.x;   // 24576, divides n4

    for (int i = blockIdx.x * blockDim.x + threadIdx.x; i < n4; i += stride) {
        float4 v = Yb[i];
        unsigned int keys[4];
        keys[0] = f2key(v.x); keys[1] = f2key(v.y);
        keys[2] = f2key(v.z); keys[3] = f2key(v.w);
        #pragma unroll
        for (int j = 0; j < 4; j++) {
            unsigned int bin = keys[j] >> 19;
            atomicAdd(&sh[bin], 1u);
            bool m = (bin >= WIN_LO_BIN) && (bin < WIN_HI_BIN);
            warp_push(b, m, keys[j]);
        }
    }
    __syncthreads();
    for (int i = threadIdx.x; i < NBINS; i += blockDim.x) {
        unsigned int c = sh[i];
        if (c) atomicAdd(&g_hist[b][i], c);
    }
}

// ---- K2: per-batch decide (window resolved?) or pick fallback bin ----
// grid (Bn), 1024 threads
__global__ void k_decide() {
    __shared__ unsigned int part[1024];
    const int b = blockIdx.x;
    const int t = threadIdx.x;

    unsigned int loc[8]; unsigned int s = 0u;
    #pragma unroll
    for (int j = 0; j < 8; j++) { loc[j] = g_hist[b][t * 8 + j]; s += loc[j]; }
    part[t] = s;
    __syncthreads();
    // suffix inclusive scan: part[t] = sum over [t..1023]
    for (int off = 1; off < 1024; off <<= 1) {
        unsigned int v = part[t] + ((t + off < 1024) ? part[t + off] : 0u);
        __syncthreads();
        part[t] = v;
        __syncthreads();
    }
    unsigned int SPt = part[t];
    unsigned int SPn = (t < 1023) ? part[t + 1] : 0u;
    unsigned int count_above = part[WIN_HI_BIN / 8];   // suffix at bin 6016
    unsigned int count_from_lo = part[WIN_LO_BIN / 8]; // suffix at bin 2176
    bool resolved = (count_above < Rn) && (Rn <= count_from_lo);

    if (resolved) {
        if (t == 0) { g_fallback[b] = 0; g_rank[b] = Rn - count_above; }
    } else {
        if (SPt >= Rn && SPn < Rn) {  // unique crossing thread
            unsigned int cum = SPn;
            unsigned int bsel = 0u, rk = 1u;
            #pragma unroll
            for (int j = 7; j >= 0; j--) {
                unsigned int c = loc[j];
                if (cum + c >= Rn) { bsel = (unsigned)(t * 8 + j); rk = Rn - cum; break; }
                cum += c;
            }
            g_fbin[b] = bsel; g_rank[b] = rk; g_fallback[b] = 1; g_cnt[b] = 0u;
        }
    }
}

// ---- K3: fallback collect (early-exit when resolved) ----
__global__ void k_collect(const float* __restrict__ Y) {
    const int b = blockIdx.y;
    if (!g_fallback[b]) return;
    const unsigned int fb = g_fbin[b];
    const float4* Yb = (const float4*)(Y + (size_t)b * Mn);
    const int n4 = Mn / 4;
    const int stride = gridDim.x * blockDim.x;
    for (int i = blockIdx.x * blockDim.x + threadIdx.x; i < n4; i += stride) {
        float4 v = Yb[i];
        unsigned int keys[4];
        keys[0] = f2key(v.x); keys[1] = f2key(v.y);
        keys[2] = f2key(v.z); keys[3] = f2key(v.w);
        #pragma unroll
        for (int j = 0; j < 4; j++) {
            bool m = ((keys[j] >> 19) == fb);
            warp_push(b, m, keys[j]);
        }
    }
}

// ---- K4: exact radix select over candidates -> g_thr[b] ----
// grid (Bn), 1024 threads
__global__ void k_select() {
    __shared__ unsigned int hist[2048];
    __shared__ unsigned int part[1024];
    __shared__ unsigned int s_digit;
    __shared__ unsigned int s_r;
    const int b = blockIdx.x;
    const int t = threadIdx.x;

    const unsigned int n = min(g_cnt[b], (unsigned)CAND_CAP);
    unsigned int r = g_rank[b];
    unsigned int pmask = 0u, pval = 0u;
    const int shifts[3] = {21, 10, 0};
    const int bitsv[3] = {11, 11, 10};

    for (int pass = 0; pass < 3; pass++) {
        const int nb = 1 << bitsv[pass];
        hist[t] = 0u; hist[t + 1024] = 0u;
        if (t == 0) { s_digit = 0u; s_r = r; }
        __syncthreads();
        for (unsigned int i = t; i < n; i += 1024u) {
            unsigned int k = g_cand[b][i];
            if ((k & pmask) == pval)
                atomicAdd(&hist[(k >> shifts[pass]) & (unsigned)(nb - 1)], 1u);
        }
        __syncthreads();
        unsigned int h0 = hist[2 * t], h1 = hist[2 * t + 1];
        part[t] = h0 + h1;
        __syncthreads();
        for (int off = 1; off < 1024; off <<= 1) {
            unsigned int v = part[t] + ((t + off < 1024) ? part[t + off] : 0u);
            __syncthreads();
            part[t] = v;
            __syncthreads();
        }
        unsigned int SPt = part[t];
        unsigned int SPn = (t < 1023) ? part[t + 1] : 0u;
        if (SPt >= r && SPn < r) {
            unsigned int cum = SPn;
            unsigned int d; unsigned int rn;
            if (cum + h1 >= r) { d = 2u * t + 1u; rn = r - cum; }
            else               { d = 2u * t;      rn = r - (cum + h1); }
            s_digit = d; s_r = rn;
        }
        __syncthreads();
        r = s_r;
        pval  |= (s_digit << shifts[pass]);
        pmask |= ((unsigned)(nb - 1)) << shifts[pass];
        __syncthreads();
    }
    if (t == 0) g_thr[b] = key2f(pval);
}

// ---- K5: write Ytr in NCHW (4 pixels / thread, float4 in + out) ----
// grid (HWn/4/256, Bn), 256 threads
__global__ void k_out(const float* __restrict__ Y, float* __restrict__ out) {
    const int b = blockIdx.y;
    const float thr = g_thr[b];
    const int g = blockIdx.x * blockDim.x + threadIdx.x;  // pixel-group id, pixels 4g..4g+3
    const float4* Yb = (const float4*)(Y + (size_t)b * Mn);
    float4 A = Yb[3 * g + 0];
    float4 Bv = Yb[3 * g + 1];
    float4 Cv = Yb[3 * g + 2];
    float4 o0, o1, o2;
    o0.x = (A.x  >= thr) ? 1.f : 0.f;  o0.y = (A.w  >= thr) ? 1.f : 0.f;
    o0.z = (Bv.z >= thr) ? 1.f : 0.f;  o0.w = (Cv.y >= thr) ? 1.f : 0.f;
    o1.x = (A.y  >= thr) ? 1.f : 0.f;  o1.y = (Bv.x >= thr) ? 1.f : 0.f;
    o1.z = (Bv.w >= thr) ? 1.f : 0.f;  o1.w = (Cv.z >= thr) ? 1.f : 0.f;
    o2.x = (A.z  >= thr) ? 1.f : 0.f;  o2.y = (Bv.y >= thr) ? 1.f : 0.f;
    o2.z = (Cv.x >= thr) ? 1.f : 0.f;  o2.w = (Cv.w >= thr) ? 1.f : 0.f;
    float4* O = (float4*)out;
    const size_t planeQ = HWn / 4;  // 262144 float4s per plane
    O[((size_t)b * 3 + 0) * planeQ + g] = o0;
    O[((size_t)b * 3 + 1) * planeQ + g] = o1;
    O[((size_t)b * 3 + 2) * planeQ + g] = o2;
}

// ---- Z0: sum of abs^2 ----
__global__ void k_zsum(const float* __restrict__ A) {
    float s = 0.f;
    const float4* A4 = (const float4*)A;
    const int n4 = HWn / 4;
    for (int i = blockIdx.x * blockDim.x + threadIdx.x; i < n4; i += gridDim.x * blockDim.x) {
        float4 v = A4[i];
        s += v.x * v.x + v.y * v.y + v.z * v.z + v.w * v.w;
    }
    #pragma unroll
    for (int o = 16; o; o >>= 1) s += __shfl_down_sync(0xffffffffu, s, o);
    __shared__ float ws[32];
    int lane = threadIdx.x & 31, w = threadIdx.x >> 5;
    if (lane == 0) ws[w] = s;
    __syncthreads();
    if (w == 0) {
        s = (lane < (int)(blockDim.x >> 5)) ? ws[lane] : 0.f;
        #pragma unroll
        for (int o = 16; o; o >>= 1) s += __shfl_down_sync(0xffffffffu, s, o);
        if (lane == 0) atomicAdd(&g_zsum, s);
    }
}

// ---- Z0: write REAL PART of normalized complex field (output stores float32) ----
// Re(Z0) = abs * cos(angle) / fro;  one float per pixel, 4 pixels/thread.
__global__ void k_zwrite(const float* __restrict__ A, const float* __restrict__ G,
                         float* __restrict__ z0out) {
    int i = blockIdx.x * blockDim.x + threadIdx.x;   // float4 group
    const int n4 = HWn / 4;
    if (i >= n4) return;
    float inv = rsqrtf(g_zsum);
    float4 a = ((const float4*)A)[i];
    float4 g = ((const float4*)G)[i];
    float4 o;
    o.x = a.x * __cosf(g.x) * inv;
    o.y = a.y * __cosf(g.y) * inv;
    o.z = a.z * __cosf(g.z) * inv;
    o.w = a.w * __cosf(g.w) * inv;
    // use accurate cosf instead if fast-math ever becomes a precision issue
    o.x = a.x * cosf(g.x) * inv;
    o.y = a.y * cosf(g.y) * inv;
    o.z = a.z * cosf(g.z) * inv;
    o.w = a.w * cosf(g.w) * inv;
    ((float4*)z0out)[i] = o;
}

extern "C" void kernel_launch(void* const* d_in, const int* in_sizes, int n_in,
                              void* d_out, int out_size) {
    const float* Y    = (const float*)d_in[0];
    const float* Zabs = (const float*)d_in[1];
    const float* Zang = (const float*)d_in[2];
    float* out = (float*)d_out;
    (void)in_sizes; (void)n_in; (void)out_size;

    // Output layout (float32): Ytr [Bn*Mn] then Re(Z0) [HWn]. Total = out_size.
    float* z0out = out + (size_t)Bn * Mn;

    k_init<<<64, 256>>>();
    k_hist<<<dim3(24, Bn), 1024>>>(Y);
    k_zsum<<<64, 256>>>(Zabs);
    k_decide<<<Bn, 1024>>>();
    k_collect<<<dim3(24, Bn), 1024>>>(Y);
    k_select<<<Bn, 1024>>>();
    k_out<<<dim3(HWn / 4 / 256, Bn), 256>>>(Y, out);
    k_zwrite<<<HWn / 4 / 256, 256>>>(Zabs, Zang, z0out);
}

// round 6
// speedup vs baseline: 1.9397x; 1.9397x over previous
#include <cuda_runtime.h>
#include <stdint.h>

#define Bn 8
#define Hn 1024
#define Wn 1024
#define Cn 3
#define Mn (Hn*Wn*Cn)          // 3145728 per batch
#define HWn (Hn*Wn)            // 1048576
#define Rn 1572864u            // ceil(M/2)
#define NBINS 8192
#define CAND_CAP 262144
#define STAGE_CAP 512
#define CW 0.00390625f         // 2^-8 window half-width
// key space: monotone uint; window (|v| < 2^-8)  <=>  key in [KLO, KHI)
#define KLO 0x44800000u
#define KHI 0xBB800000u

// ---- device scratch ----
__device__ unsigned g_hist[Bn][NBINS];
__device__ unsigned g_cand[Bn][CAND_CAP];
__device__ unsigned g_posb[Bn][CAND_CAP];
__device__ unsigned g_cnt[Bn];
__device__ unsigned g_geklo[Bn];
__device__ unsigned g_rank[Bn];
__device__ int      g_fallback[Bn];
__device__ int      g_ovf[Bn];
__device__ unsigned g_fbin[Bn];
__device__ float    g_thr[Bn];
__device__ unsigned g_thrkey[Bn];
__device__ float    g_zsum;

__device__ __forceinline__ unsigned f2key(float f) {
    unsigned u = __float_as_uint(f);
    return (u & 0x80000000u) ? ~u : (u | 0x80000000u);
}
__device__ __forceinline__ float key2f(unsigned k) {
    return (k & 0x80000000u) ? __uint_as_float(k & 0x7fffffffu)
                             : __uint_as_float(~k);
}

// ---- K0: zero replay-sensitive state ----
__global__ void k_init() {
    int tid = blockIdx.x * blockDim.x + threadIdx.x;
    int stride = gridDim.x * blockDim.x;
    unsigned* h = (unsigned*)g_hist;
    for (int i = tid; i < Bn * NBINS; i += stride) h[i] = 0u;
    if (tid < Bn) { g_cnt[tid] = 0u; g_geklo[tid] = 0u; g_ovf[tid] = 0; }
    if (tid == 0) g_zsum = 0.f;
}

// per-element: provisional select + count + window-min
__device__ __forceinline__ float selcnt(float x, int& cnt, float& wmin) {
    bool p = (x > -CW);
    cnt += p ? 1 : 0;
    wmin = fminf(wmin, fabsf(x));
    return p ? 1.0f : 0.0f;
}

// ---- K1: fused single pass over Y ----
// grid (512, Bn) x 256; thread t handles float4s 6t..6t+5 (= pixel groups 2t, 2t+1)
__global__ void k_fused(const float* __restrict__ Y, float* __restrict__ out) {
    __shared__ unsigned s_key[STAGE_CAP];
    __shared__ unsigned s_pos[STAGE_CAP];
    __shared__ unsigned s_n;
    __shared__ unsigned s_base;
    __shared__ int s_red[8];
    const int b = blockIdx.y;
    const int tid = threadIdx.x;
    if (tid == 0) s_n = 0u;
    __syncthreads();

    const int t = blockIdx.x * blockDim.x + tid;
    const float4* Y4 = (const float4*)(Y + (size_t)b * Mn);
    float4 v[6];
    #pragma unroll
    for (int k = 0; k < 6; k++) v[k] = Y4[6 * t + k];

    int cnt = 0;
    float wmin = 1e30f;
    float4* O = (float4*)out;
    const size_t planeQ = HWn / 4;

    #pragma unroll
    for (int q = 0; q < 2; q++) {
        float4 A = v[3*q], Bv = v[3*q+1], Cv = v[3*q+2];
        float4 o0, o1, o2;
        o0.x = selcnt(A.x,  cnt, wmin);  o0.y = selcnt(A.w,  cnt, wmin);
        o0.z = selcnt(Bv.z, cnt, wmin);  o0.w = selcnt(Cv.y, cnt, wmin);
        o1.x = selcnt(A.y,  cnt, wmin);  o1.y = selcnt(Bv.x, cnt, wmin);
        o1.z = selcnt(Bv.w, cnt, wmin);  o1.w = selcnt(Cv.z, cnt, wmin);
        o2.x = selcnt(A.z,  cnt, wmin);  o2.y = selcnt(Bv.y, cnt, wmin);
        o2.z = selcnt(Cv.x, cnt, wmin);  o2.w = selcnt(Cv.w, cnt, wmin);
        size_t g = (size_t)(2 * t + q);
        O[((size_t)(b * 3 + 0)) * planeQ + g] = o0;
        O[((size_t)(b * 3 + 1)) * planeQ + g] = o1;
        O[((size_t)(b * 3 + 2)) * planeQ + g] = o2;
    }

    // rare slow path: stage window candidates (key + element index) in shared
    if (wmin < CW) {
        #pragma unroll
        for (int k = 0; k < 6; k++) {
            float xs[4] = {v[k].x, v[k].y, v[k].z, v[k].w};
            #pragma unroll
            for (int j = 0; j < 4; j++) {
                float x = xs[j];
                if (fabsf(x) < CW) {
                    unsigned idx = atomicAdd(&s_n, 1u);
                    if (idx < STAGE_CAP) {
                        s_key[idx] = f2key(x);
                        s_pos[idx] = 4u * (6u * t + k) + j;
                    }
                }
            }
        }
    }

    // block-reduce count, publish staging
    #pragma unroll
    for (int o = 16; o; o >>= 1) cnt += __shfl_down_sync(0xffffffffu, cnt, o);
    if ((tid & 31) == 0) s_red[tid >> 5] = cnt;
    __syncthreads();
    if (tid == 0) {
        int sblk = 0;
        #pragma unroll
        for (int w = 0; w < 8; w++) sblk += s_red[w];
        atomicAdd(&g_geklo[b], (unsigned)sblk);
        unsigned n = s_n;
        if (n > STAGE_CAP) { g_ovf[b] = 1; n = STAGE_CAP; }
        s_base = atomicAdd(&g_cnt[b], n);
        s_n = n;
    }
    __syncthreads();
    unsigned n = s_n, base0 = s_base;
    for (unsigned i = tid; i < n; i += blockDim.x) {
        unsigned p0 = base0 + i;
        if (p0 < CAND_CAP) { g_cand[b][p0] = s_key[i]; g_posb[b][p0] = s_pos[i]; }
        else g_ovf[b] = 1;
    }
}

// ---- K2: tiny resolve decision ----
__global__ void k_decide2() {
    int t = threadIdx.x;
    if (t >= Bn) return;
    unsigned ge = g_geklo[t];
    unsigned cw = g_cnt[t];
    unsigned above = ge - cw;           // count(v >= +CW)
    bool resolved = (!g_ovf[t]) && (above < Rn) && (Rn <= ge) && (cw <= CAND_CAP);
    if (resolved) { g_fallback[t] = 0; g_rank[t] = Rn - above; }
    else          { g_fallback[t] = 1; }
}

// ---- fallback chain (gated; dormant for this input) ----
__global__ void k_hist_fb(const float* __restrict__ Y) {
    const int b = blockIdx.y;
    if (!g_fallback[b]) return;
    __shared__ unsigned sh[NBINS];
    for (int i = threadIdx.x; i < NBINS; i += blockDim.x) sh[i] = 0u;
    __syncthreads();
    const float4* Yb = (const float4*)(Y + (size_t)b * Mn);
    const int n4 = Mn / 4;
    const int stride = gridDim.x * blockDim.x;
    for (int i = blockIdx.x * blockDim.x + threadIdx.x; i < n4; i += stride) {
        float4 v = Yb[i];
        atomicAdd(&sh[f2key(v.x) >> 19], 1u);
        atomicAdd(&sh[f2key(v.y) >> 19], 1u);
        atomicAdd(&sh[f2key(v.z) >> 19], 1u);
        atomicAdd(&sh[f2key(v.w) >> 19], 1u);
    }
    __syncthreads();
    for (int i = threadIdx.x; i < NBINS; i += blockDim.x) {
        unsigned c = sh[i];
        if (c) atomicAdd(&g_hist[b][i], c);
    }
}

__global__ void k_decide_fb() {
    const int b = blockIdx.x;
    if (!g_fallback[b]) return;
    __shared__ unsigned part[1024];
    const int t = threadIdx.x;
    unsigned loc[8]; unsigned s = 0u;
    #pragma unroll
    for (int j = 0; j < 8; j++) { loc[j] = g_hist[b][t * 8 + j]; s += loc[j]; }
    part[t] = s;
    __syncthreads();
    for (int off = 1; off < 1024; off <<= 1) {
        unsigned v = part[t] + ((t + off < 1024) ? part[t + off] : 0u);
        __syncthreads();
        part[t] = v;
        __syncthreads();
    }
    unsigned SPt = part[t];
    unsigned SPn = (t < 1023) ? part[t + 1] : 0u;
    if (SPt >= Rn && SPn < Rn) {
        unsigned cum = SPn;
        unsigned bsel = 0u, rk = 1u;
        #pragma unroll
        for (int j = 7; j >= 0; j--) {
            unsigned c = loc[j];
            if (cum + c >= Rn) { bsel = (unsigned)(t * 8 + j); rk = Rn - cum; break; }
            cum += c;
        }
        g_fbin[b] = bsel; g_rank[b] = rk; g_cnt[b] = 0u;
    }
}

__global__ void k_collect_fb(const float* __restrict__ Y) {
    const int b = blockIdx.y;
    if (!g_fallback[b]) return;
    const unsigned fb = g_fbin[b];
    const float4* Yb = (const float4*)(Y + (size_t)b * Mn);
    const int n4 = Mn / 4;
    const int stride = gridDim.x * blockDim.x;
    const unsigned lane = threadIdx.x & 31u;
    for (int i = blockIdx.x * blockDim.x + threadIdx.x; i < n4; i += stride) {
        float4 v = Yb[i];
        unsigned keys[4];
        keys[0] = f2key(v.x); keys[1] = f2key(v.y);
        keys[2] = f2key(v.z); keys[3] = f2key(v.w);
        #pragma unroll
        for (int j = 0; j < 4; j++) {
            bool m = ((keys[j] >> 19) == fb);
            unsigned mask = __ballot_sync(0xffffffffu, m);
            unsigned c = __popc(mask);
            unsigned base = 0u;
            if (lane == 0u && c) base = atomicAdd(&g_cnt[b], c);
            base = __shfl_sync(0xffffffffu, base, 0);
            if (m) {
                unsigned pos = base + __popc(mask & ((1u << lane) - 1u));
                if (pos < CAND_CAP) { g_cand[b][pos] = keys[j]; g_posb[b][pos] = 4u*i + j; }
            }
        }
    }
}

// ---- K3: exact radix select over candidates -> threshold ----
__global__ void k_select() {
    __shared__ unsigned hist[2048];
    __shared__ unsigned part[1024];
    __shared__ unsigned s_digit;
    __shared__ unsigned s_r;
    const int b = blockIdx.x;
    const int t = threadIdx.x;

    const unsigned n = min(g_cnt[b], (unsigned)CAND_CAP);
    unsigned r = g_rank[b];
    unsigned pmask = 0u, pval = 0u;
    const int shifts[3] = {21, 10, 0};
    const int bitsv[3] = {11, 11, 10};

    for (int pass = 0; pass < 3; pass++) {
        const int nb = 1 << bitsv[pass];
        hist[t] = 0u; hist[t + 1024] = 0u;
        if (t == 0) { s_digit = 0u; s_r = r; }
        __syncthreads();
        for (unsigned i = t; i < n; i += 1024u) {
            unsigned k = g_cand[b][i];
            if ((k & pmask) == pval)
                atomicAdd(&hist[(k >> shifts[pass]) & (unsigned)(nb - 1)], 1u);
        }
        __syncthreads();
        unsigned h0 = hist[2 * t], h1 = hist[2 * t + 1];
        part[t] = h0 + h1;
        __syncthreads();
        for (int off = 1; off < 1024; off <<= 1) {
            unsigned v = part[t] + ((t + off < 1024) ? part[t + off] : 0u);
            __syncthreads();
            part[t] = v;
            __syncthreads();
        }
        unsigned SPt = part[t];
        unsigned SPn = (t < 1023) ? part[t + 1] : 0u;
        if (SPt >= r && SPn < r) {
            unsigned cum = SPn;
            unsigned d, rn;
            if (cum + h1 >= r) { d = 2u * t + 1u; rn = r - cum; }
            else               { d = 2u * t;      rn = r - (cum + h1); }
            s_digit = d; s_r = rn;
        }
        __syncthreads();
        r = s_r;
        pval  |= (s_digit << shifts[pass]);
        pmask |= ((unsigned)(nb - 1)) << shifts[pass];
        __syncthreads();
    }
    if (t == 0) { g_thrkey[b] = pval; g_thr[b] = key2f(pval); }
}

// ---- K4: slow full output for fallback batches ----
__global__ void k_out_slow(const float* __restrict__ Y, float* __restrict__ out) {
    const int b = blockIdx.y;
    if (!g_fallback[b]) return;
    const float thr = g_thr[b];
    const int g = blockIdx.x * blockDim.x + threadIdx.x;
    const float4* Yb = (const float4*)(Y + (size_t)b * Mn);
    float4 A = Yb[3*g+0], Bv = Yb[3*g+1], Cv = Yb[3*g+2];
    float4 o0, o1, o2;
    o0.x = (A.x  >= thr) ? 1.f : 0.f;  o0.y = (A.w  >= thr) ? 1.f : 0.f;
    o0.z = (Bv.z >= thr) ? 1.f : 0.f;  o0.w = (Cv.y >= thr) ? 1.f : 0.f;
    o1.x = (A.y  >= thr) ? 1.f : 0.f;  o1.y = (Bv.x >= thr) ? 1.f : 0.f;
    o1.z = (Bv.w >= thr) ? 1.f : 0.f;  o1.w = (Cv.z >= thr) ? 1.f : 0.f;
    o2.x = (A.z  >= thr) ? 1.f : 0.f;  o2.y = (Bv.y >= thr) ? 1.f : 0.f;
    o2.z = (Cv.x >= thr) ? 1.f : 0.f;  o2.w = (Cv.w >= thr) ? 1.f : 0.f;
    float4* O = (float4*)out;
    const size_t planeQ = HWn / 4;
    O[((size_t)b * 3 + 0) * planeQ + g] = o0;
    O[((size_t)b * 3 + 1) * planeQ + g] = o1;
    O[((size_t)b * 3 + 2) * planeQ + g] = o2;
}

// ---- K5: fixup provisional output (resolved batches): flip below-thr window elems to 0
__global__ void k_fixup(float* __restrict__ out) {
    const int b = blockIdx.y;
    if (g_fallback[b]) return;
    const unsigned n = min(g_cnt[b], (unsigned)CAND_CAP);
    const unsigned tk = g_thrkey[b];
    const int stride = gridDim.x * blockDim.x;
    for (unsigned i = blockIdx.x * blockDim.x + threadIdx.x; i < n; i += stride) {
        if (g_cand[b][i] < tk) {
            unsigned e = g_posb[b][i];
            unsigned hw = e / 3u;
            unsigned c = e - hw * 3u;
            out[((size_t)(b * 3 + c)) * HWn + hw] = 0.0f;
        }
    }
}

// ---- Z0 ----
__global__ void k_zsum(const float* __restrict__ A) {
    float s = 0.f;
    const float4* A4 = (const float4*)A;
    const int n4 = HWn / 4;
    for (int i = blockIdx.x * blockDim.x + threadIdx.x; i < n4; i += gridDim.x * blockDim.x) {
        float4 v = A4[i];
        s += v.x * v.x + v.y * v.y + v.z * v.z + v.w * v.w;
    }
    #pragma unroll
    for (int o = 16; o; o >>= 1) s += __shfl_down_sync(0xffffffffu, s, o);
    __shared__ float ws[32];
    int lane = threadIdx.x & 31, w = threadIdx.x >> 5;
    if (lane == 0) ws[w] = s;
    __syncthreads();
    if (w == 0) {
        s = (lane < (int)(blockDim.x >> 5)) ? ws[lane] : 0.f;
        #pragma unroll
        for (int o = 16; o; o >>= 1) s += __shfl_down_sync(0xffffffffu, s, o);
        if (lane == 0) atomicAdd(&g_zsum, s);
    }
}

__global__ void k_zwrite(const float* __restrict__ A, const float* __restrict__ G,
                         float* __restrict__ z0out) {
    int i = blockIdx.x * blockDim.x + threadIdx.x;
    const int n4 = HWn / 4;
    if (i >= n4) return;
    float inv = rsqrtf(g_zsum);
    float4 a = ((const float4*)A)[i];
    float4 g = ((const float4*)G)[i];
    float4 o;
    o.x = a.x * cosf(g.x) * inv;
    o.y = a.y * cosf(g.y) * inv;
    o.z = a.z * cosf(g.z) * inv;
    o.w = a.w * cosf(g.w) * inv;
    ((float4*)z0out)[i] = o;
}

extern "C" void kernel_launch(void* const* d_in, const int* in_sizes, int n_in,
                              void* d_out, int out_size) {
    const float* Y    = (const float*)d_in[0];
    const float* Zabs = (const float*)d_in[1];
    const float* Zang = (const float*)d_in[2];
    float* out = (float*)d_out;
    (void)in_sizes; (void)n_in; (void)out_size;

    float* z0out = out + (size_t)Bn * Mn;

    k_init<<<64, 256>>>();
    k_fused<<<dim3(512, Bn), 256>>>(Y, out);
    k_zsum<<<64, 256>>>(Zabs);
    k_decide2<<<1, 32>>>();
    k_hist_fb<<<dim3(24, Bn), 1024>>>(Y);
    k_decide_fb<<<Bn, 1024>>>();
    k_collect_fb<<<dim3(24, Bn), 1024>>>(Y);
    k_select<<<Bn, 1024>>>();
    k_out_slow<<<dim3(1024, Bn), 256>>>(Y, out);
    k_fixup<<<dim3(16, Bn), 256>>>(out);
    k_zwrite<<<HWn / 4 / 256, 256>>>(Zabs, Zang, z0out);
}